// round 15
// baseline (speedup 1.0000x reference)
#include <cuda_runtime.h>
#include <cuda_fp16.h>
#include <cstdint>
#include <cstddef>

#define M_BATCH 8192
#define D_DIM   512
#define H_DIM   2048
#define N_STEPS 10

// ---------------- scratch (device globals; no allocation allowed) ----------
__device__ float  g_y [M_BATCH * D_DIM];            // fp32 state
__device__ float  g_k1[M_BATCH * D_DIM];            // fp32 k1
__device__ __half g_yr[M_BATCH * D_DIM];            // fp16 copy of state (G1 A)
__device__ __half g_yt[M_BATCH * D_DIM];            // fp16 y + dt*k1   (G1 A)
__device__ __half g_h [M_BATCH * H_DIM];            // fp16 tanh hidden (G2 A)
__device__ __half g_W1t[(size_t)H_DIM * D_DIM];     // W1^T fp16, [N=H, K=D]
__device__ __half g_W2t[(size_t)D_DIM * H_DIM];     // W2^T fp16, [N=D, K=H]
__device__ int    g_cnt[40 * 64];                   // per-(phase, bm-row) counters

// ---------------- work-list constants ----------------------------------------
constexpr int TILES_G1   = 1024;   // 64 x 16 tiles of 128x128 (out 8192x2048)
constexpr int TILES_G2   = 256;    // 64 x  4 tiles of 128x128 (out 8192x512)
constexpr int TILES_STEP = 2 * TILES_G1 + 2 * TILES_G2;   // 2560
constexpr int TILES_TOT  = N_STEPS * TILES_STEP;          // 25600

// ---------------- helpers ----------------------------------------------------
__device__ __forceinline__ uint32_t smem_u32(const void* p) {
    uint32_t a;
    asm("{ .reg .u64 t; cvta.to.shared.u64 t, %1; cvt.u32.u64 %0, t; }" : "=r"(a) : "l"(p));
    return a;
}
__device__ __forceinline__ float tanh_fast(float x) {       // MUFU.TANH
    float y;
    asm("tanh.approx.f32 %0, %1;" : "=f"(y) : "f"(x));
    return y;
}
__device__ __forceinline__ void mma_f16(float c[4], const uint32_t a[4], const uint32_t b[2]) {
    asm volatile(
        "mma.sync.aligned.m16n8k16.row.col.f32.f16.f16.f32 "
        "{%0,%1,%2,%3}, {%4,%5,%6,%7}, {%8,%9}, {%0,%1,%2,%3};"
        : "+f"(c[0]), "+f"(c[1]), "+f"(c[2]), "+f"(c[3])
        : "r"(a[0]), "r"(a[1]), "r"(a[2]), "r"(a[3]), "r"(b[0]), "r"(b[1]));
}
__device__ __forceinline__ void ldsm_x4(uint32_t r[4], uint32_t addr) {
    asm volatile("ldmatrix.sync.aligned.m8n8.x4.shared.b16 {%0,%1,%2,%3}, [%4];"
        : "=r"(r[0]), "=r"(r[1]), "=r"(r[2]), "=r"(r[3]) : "r"(addr));
}
__device__ __forceinline__ int ld_acquire(const int* p) {
    int v;
    asm volatile("ld.acquire.gpu.global.b32 %0, [%1];" : "=r"(v) : "l"(p) : "memory");
    return v;
}
#define CP_ASYNC16(dst, src) \
    asm volatile("cp.async.cg.shared.global [%0], [%1], 16;" :: "r"(dst), "l"(src))
#define CP_COMMIT() asm volatile("cp.async.commit_group;" ::: "memory")
#define CP_WAIT(n)  asm volatile("cp.async.wait_group %0;" :: "n"(n) : "memory")

// ---------------- GEMM config ------------------------------------------------
// CTA tile 128x128, BK=64 (fp16), 3 smem stages, 128 threads (4 warps 2m x 2n,
// warp tile 64x64). Rows 128B with XOR-16B-chunk swizzle: chunk' = chunk^(row&7).
constexpr int ROWB  = 128;
constexpr int ASZ   = 128 * ROWB;          // 16384 B per operand stage
constexpr int STGB  = 2 * ASZ;             // 32768 B per stage (A + B)
constexpr int NSTG  = 3;
constexpr int SMEM_TOTAL = NSTG * STGB;    // 98304 B -> 2 CTAs/SM

// B-operand loader for stage of tile kt (weights; dependency-free)
__device__ __forceinline__ void load_B_stage(
    uint32_t smb, const __half* __restrict__ Bw, int bn, int K, int kt)
{
    const int tid = threadIdx.x;
    const int s = kt % NSTG;
    const uint32_t sb = smb + s * STGB + ASZ;
    #pragma unroll
    for (int i = 0; i < 8; i++) {
        const int t   = tid + i * 128;
        const int row = t >> 3;
        const int ch  = t & 7;
        const uint32_t off = (uint32_t)(row * ROWB + ((ch ^ (row & 7)) << 4));
        CP_ASYNC16(sb + off, Bw + (size_t)(bn + row) * K + kt * 64 + ch * 8);
    }
}

// One 128x128 output tile of C = A @ Bw^T (+ fused epilogue by mode).
// PRECONDITION: B operand for stages 0,1 already issued as ONE cp.async group
// (done by the scheduler BEFORE the dependency spin-wait).
// mode 0: Ch = fp16(tanh(acc + bias))
// mode 1: Cf = acc + bias (k1, fp32);  C2h = fp16(yin + 0.1*k1)   (yt)
// mode 2: yn = yin + 0.05*(k1in + (acc+bias)); Cf = yn; C2h = fp16(yn)
__device__ __forceinline__ void do_tile(
    int mode, int bm, int bn,
    const __half* __restrict__ A, const __half* __restrict__ Bw,
    const float* __restrict__ bias,
    float* __restrict__ Cf, __half* __restrict__ Ch, __half* __restrict__ C2h,
    const float* __restrict__ yin, const float* __restrict__ k1in,
    int N, int K, uint32_t smb)
{
    const int tid  = threadIdx.x;
    const int lane = tid & 31;
    const int wid  = tid >> 5;
    const int wm   = (wid & 1) * 64;
    const int wn   = (wid >> 1) * 64;
    const int g    = lane >> 2;
    const int tig  = lane & 3;
    const int ktiles = K / 64;

    const int e = lane & 7;
    const int m = lane >> 3;
    const uint32_t rowA = (uint32_t)(wm + (m & 1) * 8 + e) * ROWB;
    const int      ca   = m >> 1;
    const uint32_t rowB = (uint32_t)(wn + (m >> 1) * 8 + e) * ROWB;
    const int      cb   = m & 1;

    float acc[4][8][4];
    #pragma unroll
    for (int i = 0; i < 4; i++)
        #pragma unroll
        for (int j = 0; j < 8; j++)
            #pragma unroll
            for (int el = 0; el < 4; el++)
                acc[i][j][el] = 0.0f;

    // A-operand loader for stage of tile kt
    auto load_A_stage = [&](int kt) {
        const int s = kt % NSTG;
        const uint32_t sa = smb + s * STGB;
        #pragma unroll
        for (int i = 0; i < 8; i++) {
            const int t   = tid + i * 128;
            const int row = t >> 3;
            const int ch  = t & 7;
            const uint32_t off = (uint32_t)(row * ROWB + ((ch ^ (row & 7)) << 4));
            CP_ASYNC16(sa + off, A + (size_t)(bm + row) * K + kt * 64 + ch * 8);
        }
    };

    // ---- prologue: A for stages 0,1 (B already in flight from scheduler) ----
    #pragma unroll
    for (int kt = 0; kt < NSTG - 1; kt++) {
        load_A_stage(kt);
        CP_COMMIT();
    }
    // groups now: [B01][A0][A1]

    // ---- mainloop ----
    for (int kt = 0; kt < ktiles; kt++) {
        if (kt + 1 < ktiles) { CP_WAIT(1); }
        else                 { CP_WAIT(0); }
        __syncthreads();

        if (kt + NSTG - 1 < ktiles) {
            load_B_stage(smb, Bw, bn, K, kt + NSTG - 1);
            load_A_stage(kt + NSTG - 1);
            CP_COMMIT();
        }

        const int s = kt % NSTG;
        const uint32_t sa = smb + s * STGB;
        const uint32_t sb = sa + ASZ;

        #pragma unroll
        for (int kq = 0; kq < 4; kq++) {
            uint32_t af[4][4], bf[8][2];
            #pragma unroll
            for (int mt = 0; mt < 4; mt++) {
                const uint32_t addr = sa + rowA + (uint32_t)(mt * 16) * ROWB
                                    + (uint32_t)(((2 * kq + ca) ^ e) << 4);
                ldsm_x4(af[mt], addr);
            }
            #pragma unroll
            for (int ntp = 0; ntp < 4; ntp++) {
                uint32_t r[4];
                const uint32_t addr = sb + rowB + (uint32_t)(ntp * 16) * ROWB
                                    + (uint32_t)(((2 * kq + cb) ^ e) << 4);
                ldsm_x4(r, addr);
                bf[2 * ntp + 0][0] = r[0];
                bf[2 * ntp + 0][1] = r[1];
                bf[2 * ntp + 1][0] = r[2];
                bf[2 * ntp + 1][1] = r[3];
            }
            #pragma unroll
            for (int mt = 0; mt < 4; mt++)
                #pragma unroll
                for (int nt = 0; nt < 8; nt++)
                    mma_f16(acc[mt][nt], af[mt], bf[nt]);
        }
    }

    // ---- fused epilogue ----
    #pragma unroll
    for (int mt = 0; mt < 4; mt++) {
        #pragma unroll
        for (int nt = 0; nt < 8; nt++) {
            const int col = bn + wn + nt * 8 + tig * 2;
            const float bv0 = __ldg(&bias[col]);
            const float bv1 = __ldg(&bias[col + 1]);
            #pragma unroll
            for (int half = 0; half < 2; half++) {
                const int row = bm + wm + mt * 16 + g + half * 8;
                const size_t idx = (size_t)row * N + col;
                const float v0 = acc[mt][nt][half * 2 + 0] + bv0;
                const float v1 = acc[mt][nt][half * 2 + 1] + bv1;
                if (mode == 0) {
                    *reinterpret_cast<__half2*>(Ch + idx) =
                        __floats2half2_rn(tanh_fast(v0), tanh_fast(v1));
                } else if (mode == 1) {
                    const float2 yv = *reinterpret_cast<const float2*>(yin + idx);
                    float2 o;  o.x = v0;  o.y = v1;
                    *reinterpret_cast<float2*>(Cf + idx) = o;
                    *reinterpret_cast<__half2*>(C2h + idx) =
                        __floats2half2_rn(yv.x + 0.1f * v0, yv.y + 0.1f * v1);
                } else {
                    const float2 yv = *reinterpret_cast<const float2*>(yin + idx);
                    const float2 kv = *reinterpret_cast<const float2*>(k1in + idx);
                    float2 o;
                    o.x = yv.x + 0.05f * (kv.x + v0);
                    o.y = yv.y + 0.05f * (kv.y + v1);
                    *reinterpret_cast<float2*>(Cf + idx) = o;
                    *reinterpret_cast<__half2*>(C2h + idx) = __floats2half2_rn(o.x, o.y);
                }
            }
        }
    }
}

// ---------------- persistent scheduler kernel ---------------------------------
__global__ void __launch_bounds__(128, 2)
heun_persistent(const float* __restrict__ y0, const float* __restrict__ b1,
                const float* __restrict__ b2, float* __restrict__ out, int nCTA)
{
    extern __shared__ char sm[];
    const uint32_t smb = smem_u32(sm);
    const int tid = threadIdx.x;

    for (int item = blockIdx.x; item < TILES_TOT; item += nCTA) {
        // ---- decode work item -> (step, q, tile) ----
        const int step = item / TILES_STEP;
        const int r    = item - step * TILES_STEP;
        int q, t;
        if      (r < TILES_G1)                 { q = 0; t = r; }
        else if (r < TILES_G1 + TILES_G2)      { q = 1; t = r - TILES_G1; }
        else if (r < 2 * TILES_G1 + TILES_G2)  { q = 2; t = r - TILES_G1 - TILES_G2; }
        else                                   { q = 3; t = r - 2 * TILES_G1 - TILES_G2; }
        const int phase = step * 4 + q;
        const bool isG1 = (q & 1) == 0;
        const int bmIdx = isG1 ? (t >> 4) : (t >> 2);
        const int bn    = (isG1 ? (t & 15) : (t & 3)) * 128;
        const int bm    = bmIdx * 128;

        // ---- prefetch THIS tile's B (weights; dependency-free) BEFORE dep-wait
        const __half* Bw = isG1 ? g_W1t : g_W2t;
        const int     Kd = isG1 ? D_DIM : H_DIM;
        load_B_stage(smb, Bw, bn, Kd, 0);
        load_B_stage(smb, Bw, bn, Kd, 1);
        CP_COMMIT();                       // one group: [B01]

        // ---- wait for producer phase (per bm row); B loads fly meanwhile ----
        if (phase > 0) {
            const int target = isG1 ? 4 : 16;     // prev phase tiles per bm row
            const int* cp = &g_cnt[(phase - 1) * 64 + bmIdx];
            if (tid == 0) {
                while (ld_acquire(cp) < target) __nanosleep(64);
            }
            __syncthreads();
        }

        // ---- dispatch ----
        const float* ycur = (step == 0) ? y0 : g_y;
        if (isG1) {
            const __half* A = (q == 0) ? g_yr : g_yt;
            do_tile(0, bm, bn, A, Bw, b1,
                    nullptr, g_h, nullptr, nullptr, nullptr,
                    H_DIM, Kd, smb);
        } else if (q == 1) {
            do_tile(1, bm, bn, g_h, Bw, b2,
                    g_k1, nullptr, g_yt, ycur, nullptr,
                    D_DIM, Kd, smb);
        } else {
            float* yo = (step == N_STEPS - 1) ? out : g_y;
            do_tile(2, bm, bn, g_h, Bw, b2,
                    yo, nullptr, g_yr, ycur, g_k1,
                    D_DIM, Kd, smb);
        }

        // ---- publish completion ----
        __syncthreads();
        if (tid == 0) {
            __threadfence();
            atomicAdd(&g_cnt[phase * 64 + bmIdx], 1);
        }
    }
}

// ---------------- prep kernels ------------------------------------------------
__global__ void transpose_half(const float* __restrict__ in, __half* __restrict__ out,
                               int R, int C)
{
    __shared__ float t[32][33];
    const int bx = blockIdx.x * 32, by = blockIdx.y * 32;
    #pragma unroll
    for (int j = 0; j < 32; j += 8)
        t[threadIdx.y + j][threadIdx.x] = in[(size_t)(by + threadIdx.y + j) * C + bx + threadIdx.x];
    __syncthreads();
    #pragma unroll
    for (int j = 0; j < 32; j += 8)
        out[(size_t)(bx + threadIdx.y + j) * R + by + threadIdx.x] =
            __float2half_rn(t[threadIdx.x][threadIdx.y + j]);
}

// fp32->fp16 state copy, fused with counter reset
__global__ void prep_state(const float* __restrict__ in, __half* __restrict__ out, int n4)
{
    const int i = blockIdx.x * blockDim.x + threadIdx.x;
    if (i < 40 * 64) g_cnt[i] = 0;
    if (i < n4) {
        const float4 v = reinterpret_cast<const float4*>(in)[i];
        reinterpret_cast<__half2*>(out)[i * 2 + 0] = __floats2half2_rn(v.x, v.y);
        reinterpret_cast<__half2*>(out)[i * 2 + 1] = __floats2half2_rn(v.z, v.w);
    }
}

// ---------------- launch --------------------------------------------------------
extern "C" void kernel_launch(void* const* d_in, const int* in_sizes, int n_in,
                              void* d_out, int out_size)
{
    const float* y0 = (const float*)d_in[0];
    const float* W1 = (const float*)d_in[1];
    const float* b1 = (const float*)d_in[2];
    const float* W2 = (const float*)d_in[3];
    const float* b2 = (const float*)d_in[4];
    float* out = (float*)d_out;

    __half *pyr, *pW1t, *pW2t;
    cudaGetSymbolAddress((void**)&pyr,  g_yr);
    cudaGetSymbolAddress((void**)&pW1t, g_W1t);
    cudaGetSymbolAddress((void**)&pW2t, g_W2t);

    cudaFuncSetAttribute(heun_persistent,
                         cudaFuncAttributeMaxDynamicSharedMemorySize, SMEM_TOTAL);

    // grid: all CTAs must be co-resident (spin-wait safety)
    int dev = 0, sms = 0, occ = 0;
    cudaGetDevice(&dev);
    cudaDeviceGetAttribute(&sms, cudaDevAttrMultiProcessorCount, dev);
    cudaOccupancyMaxActiveBlocksPerMultiprocessor(&occ, heun_persistent, 128, SMEM_TOTAL);
    if (occ < 1) occ = 1;
    if (occ > 2) occ = 2;
    const int nCTA = sms * occ;

    // prep: weights -> K-major fp16; y0 -> fp16 copy + counter reset
    transpose_half<<<dim3(H_DIM / 32, D_DIM / 32), dim3(32, 8)>>>(W1, pW1t, D_DIM, H_DIM);
    transpose_half<<<dim3(D_DIM / 32, H_DIM / 32), dim3(32, 8)>>>(W2, pW2t, H_DIM, D_DIM);
    {
        const int n4 = M_BATCH * D_DIM / 4;
        prep_state<<<(n4 + 255) / 256, 256>>>(y0, pyr, n4);
    }

    heun_persistent<<<nCTA, 128, SMEM_TOTAL>>>(y0, b1, b2, out, nCTA);
}

// round 16
// speedup vs baseline: 1.0243x; 1.0243x over previous
#include <cuda_runtime.h>
#include <cuda_fp16.h>
#include <cstdint>
#include <cstddef>

#define M_BATCH 8192
#define D_DIM   512
#define H_DIM   2048
#define N_STEPS 10

// ---------------- scratch (device globals; no allocation allowed) ----------
__device__ float  g_y [M_BATCH * D_DIM];            // fp32 state
__device__ float  g_k1[M_BATCH * D_DIM];            // fp32 k1
__device__ __half g_yr[M_BATCH * D_DIM];            // fp16 copy of state (G1 A)
__device__ __half g_yt[M_BATCH * D_DIM];            // fp16 y + dt*k1   (G1 A)
__device__ __half g_h [M_BATCH * H_DIM];            // fp16 tanh hidden (G2 A)
__device__ __half g_W1t[(size_t)H_DIM * D_DIM];     // W1^T fp16, [N=H, K=D]
__device__ __half g_W2t[(size_t)D_DIM * H_DIM];     // W2^T fp16, [N=D, K=H]
__device__ int    g_cnt[40 * 64];                   // per-(phase, bm-row) counters

// ---------------- work-list constants ----------------------------------------
constexpr int TILES_G1   = 1024;   // 64 x 16 tiles of 128x128 (out 8192x2048)
constexpr int TILES_G2   = 256;    // 64 x  4 tiles of 128x128 (out 8192x512)
constexpr int TILES_STEP = 2 * TILES_G1 + 2 * TILES_G2;   // 2560
constexpr int TILES_TOT  = N_STEPS * TILES_STEP;          // 25600

// ---------------- helpers ----------------------------------------------------
__device__ __forceinline__ uint32_t smem_u32(const void* p) {
    uint32_t a;
    asm("{ .reg .u64 t; cvta.to.shared.u64 t, %1; cvt.u32.u64 %0, t; }" : "=r"(a) : "l"(p));
    return a;
}
__device__ __forceinline__ float tanh_fast(float x) {       // MUFU.TANH
    float y;
    asm("tanh.approx.f32 %0, %1;" : "=f"(y) : "f"(x));
    return y;
}
__device__ __forceinline__ void mma_f16(float c[4], const uint32_t a[4], const uint32_t b[2]) {
    asm volatile(
        "mma.sync.aligned.m16n8k16.row.col.f32.f16.f16.f32 "
        "{%0,%1,%2,%3}, {%4,%5,%6,%7}, {%8,%9}, {%0,%1,%2,%3};"
        : "+f"(c[0]), "+f"(c[1]), "+f"(c[2]), "+f"(c[3])
        : "r"(a[0]), "r"(a[1]), "r"(a[2]), "r"(a[3]), "r"(b[0]), "r"(b[1]));
}
__device__ __forceinline__ void ldsm_x4(uint32_t r[4], uint32_t addr) {
    asm volatile("ldmatrix.sync.aligned.m8n8.x4.shared.b16 {%0,%1,%2,%3}, [%4];"
        : "=r"(r[0]), "=r"(r[1]), "=r"(r[2]), "=r"(r[3]) : "r"(addr));
}
__device__ __forceinline__ int ld_acquire(const int* p) {
    int v;
    asm volatile("ld.acquire.gpu.global.b32 %0, [%1];" : "=r"(v) : "l"(p) : "memory");
    return v;
}
#define CP_ASYNC16(dst, src) \
    asm volatile("cp.async.cg.shared.global [%0], [%1], 16;" :: "r"(dst), "l"(src))
#define CP_COMMIT() asm volatile("cp.async.commit_group;" ::: "memory")
#define CP_WAIT(n)  asm volatile("cp.async.wait_group %0;" :: "n"(n) : "memory")

// ---------------- GEMM config ------------------------------------------------
// CTA tile 128x128, BK=64 (fp16), 3 smem stages, 128 threads (4 warps 2m x 2n,
// warp tile 64x64). Rows 128B with XOR-16B-chunk swizzle: chunk' = chunk^(row&7).
constexpr int ROWB  = 128;
constexpr int ASZ   = 128 * ROWB;          // 16384 B per operand stage
constexpr int STGB  = 2 * ASZ;             // 32768 B per stage (A + B)
constexpr int NSTG  = 3;
constexpr int SMEM_TOTAL = NSTG * STGB;    // 98304 B -> 2 CTAs/SM

// One 128x128 output tile of C = A @ Bw^T (+ fused epilogue by mode).
// mode 0: Ch = fp16(tanh(acc + bias))
// mode 1: Cf = acc + bias (k1, fp32);  C2h = fp16(yin + 0.1*k1)   (yt)
// mode 2: yn = yin + 0.05*(k1in + (acc+bias)); Cf = yn; C2h = fp16(yn)
__device__ __forceinline__ void do_tile(
    int mode, int bm, int bn,
    const __half* __restrict__ A, const __half* __restrict__ Bw,
    const float* __restrict__ bias,
    float* __restrict__ Cf, __half* __restrict__ Ch, __half* __restrict__ C2h,
    const float* __restrict__ yin, const float* __restrict__ k1in,
    int N, int K, uint32_t smb)
{
    const int tid  = threadIdx.x;
    const int lane = tid & 31;
    const int wid  = tid >> 5;
    const int wm   = (wid & 1) * 64;
    const int wn   = (wid >> 1) * 64;
    const int g    = lane >> 2;
    const int tig  = lane & 3;
    const int ktiles = K / 64;

    const int e = lane & 7;
    const int m = lane >> 3;
    const uint32_t rowA = (uint32_t)(wm + (m & 1) * 8 + e) * ROWB;
    const int      ca   = m >> 1;
    const uint32_t rowB = (uint32_t)(wn + (m >> 1) * 8 + e) * ROWB;
    const int      cb   = m & 1;

    float acc[4][8][4];
    #pragma unroll
    for (int i = 0; i < 4; i++)
        #pragma unroll
        for (int j = 0; j < 8; j++)
            #pragma unroll
            for (int el = 0; el < 4; el++)
                acc[i][j][el] = 0.0f;

    auto load_tile = [&](int kt) {
        const int s = kt % NSTG;
        const uint32_t sa = smb + s * STGB;
        const uint32_t sb = sa + ASZ;
        #pragma unroll
        for (int i = 0; i < 8; i++) {
            const int t   = tid + i * 128;
            const int row = t >> 3;
            const int ch  = t & 7;
            const uint32_t off = (uint32_t)(row * ROWB + ((ch ^ (row & 7)) << 4));
            CP_ASYNC16(sa + off, A  + (size_t)(bm + row) * K + kt * 64 + ch * 8);
            CP_ASYNC16(sb + off, Bw + (size_t)(bn + row) * K + kt * 64 + ch * 8);
        }
    };

    #pragma unroll
    for (int kt = 0; kt < NSTG - 1; kt++) {
        if (kt < ktiles) load_tile(kt);
        CP_COMMIT();
    }

    for (int kt = 0; kt < ktiles; kt++) {
        if (kt + 1 < ktiles) { CP_WAIT(1); }
        else                 { CP_WAIT(0); }
        __syncthreads();

        if (kt + NSTG - 1 < ktiles) {
            load_tile(kt + NSTG - 1);
            CP_COMMIT();
        }

        const int s = kt % NSTG;
        const uint32_t sa = smb + s * STGB;
        const uint32_t sb = sa + ASZ;

        #pragma unroll
        for (int kq = 0; kq < 4; kq++) {
            uint32_t af[4][4], bf[8][2];
            #pragma unroll
            for (int mt = 0; mt < 4; mt++) {
                const uint32_t addr = sa + rowA + (uint32_t)(mt * 16) * ROWB
                                    + (uint32_t)(((2 * kq + ca) ^ e) << 4);
                ldsm_x4(af[mt], addr);
            }
            #pragma unroll
            for (int ntp = 0; ntp < 4; ntp++) {
                uint32_t r[4];
                const uint32_t addr = sb + rowB + (uint32_t)(ntp * 16) * ROWB
                                    + (uint32_t)(((2 * kq + cb) ^ e) << 4);
                ldsm_x4(r, addr);
                bf[2 * ntp + 0][0] = r[0];
                bf[2 * ntp + 0][1] = r[1];
                bf[2 * ntp + 1][0] = r[2];
                bf[2 * ntp + 1][1] = r[3];
            }
            #pragma unroll
            for (int mt = 0; mt < 4; mt++)
                #pragma unroll
                for (int nt = 0; nt < 8; nt++)
                    mma_f16(acc[mt][nt], af[mt], bf[nt]);
        }
    }

    // fused epilogue
    #pragma unroll
    for (int mt = 0; mt < 4; mt++) {
        #pragma unroll
        for (int nt = 0; nt < 8; nt++) {
            const int col = bn + wn + nt * 8 + tig * 2;
            const float bv0 = __ldg(&bias[col]);
            const float bv1 = __ldg(&bias[col + 1]);
            #pragma unroll
            for (int half = 0; half < 2; half++) {
                const int row = bm + wm + mt * 16 + g + half * 8;
                const size_t idx = (size_t)row * N + col;
                const float v0 = acc[mt][nt][half * 2 + 0] + bv0;
                const float v1 = acc[mt][nt][half * 2 + 1] + bv1;
                if (mode == 0) {
                    *reinterpret_cast<__half2*>(Ch + idx) =
                        __floats2half2_rn(tanh_fast(v0), tanh_fast(v1));
                } else if (mode == 1) {
                    const float2 yv = *reinterpret_cast<const float2*>(yin + idx);
                    float2 o;  o.x = v0;  o.y = v1;
                    *reinterpret_cast<float2*>(Cf + idx) = o;
                    *reinterpret_cast<__half2*>(C2h + idx) =
                        __floats2half2_rn(yv.x + 0.1f * v0, yv.y + 0.1f * v1);
                } else {
                    const float2 yv = *reinterpret_cast<const float2*>(yin + idx);
                    const float2 kv = *reinterpret_cast<const float2*>(k1in + idx);
                    float2 o;
                    o.x = yv.x + 0.05f * (kv.x + v0);
                    o.y = yv.y + 0.05f * (kv.y + v1);
                    *reinterpret_cast<float2*>(Cf + idx) = o;
                    *reinterpret_cast<__half2*>(C2h + idx) = __floats2half2_rn(o.x, o.y);
                }
            }
        }
    }
}

// ---------------- persistent scheduler kernel ---------------------------------
__global__ void __launch_bounds__(128, 2)
heun_persistent(const float* __restrict__ y0, const float* __restrict__ b1,
                const float* __restrict__ b2, float* __restrict__ out, int nCTA)
{
    extern __shared__ char sm[];
    const uint32_t smb = smem_u32(sm);
    const int tid = threadIdx.x;

    for (int item = blockIdx.x; item < TILES_TOT; item += nCTA) {
        // ---- decode work item -> (step, q, tile) ----
        const int step = item / TILES_STEP;
        const int r    = item - step * TILES_STEP;
        int q, t;
        if      (r < TILES_G1)                 { q = 0; t = r; }
        else if (r < TILES_G1 + TILES_G2)      { q = 1; t = r - TILES_G1; }
        else if (r < 2 * TILES_G1 + TILES_G2)  { q = 2; t = r - TILES_G1 - TILES_G2; }
        else                                   { q = 3; t = r - 2 * TILES_G1 - TILES_G2; }
        const int phase = step * 4 + q;
        const bool isG1 = (q & 1) == 0;
        const int bmIdx = isG1 ? (t >> 4) : (t >> 2);
        const int bn    = (isG1 ? (t & 15) : (t & 3)) * 128;
        const int bm    = bmIdx * 128;

        // ---- wait for producer phase (per bm row) ----
        if (phase > 0) {
            const int target = isG1 ? 4 : 16;     // prev phase tiles per bm row
            const int* cp = &g_cnt[(phase - 1) * 64 + bmIdx];
            if (tid == 0) {
                while (ld_acquire(cp) < target) __nanosleep(64);
            }
            __syncthreads();
        }

        // ---- dispatch ----
        const float* ycur = (step == 0) ? y0 : g_y;
        if (isG1) {
            const __half* A = (q == 0) ? g_yr : g_yt;
            do_tile(0, bm, bn, A, g_W1t, b1,
                    nullptr, g_h, nullptr, nullptr, nullptr,
                    H_DIM, D_DIM, smb);
        } else if (q == 1) {
            do_tile(1, bm, bn, g_h, g_W2t, b2,
                    g_k1, nullptr, g_yt, ycur, nullptr,
                    D_DIM, H_DIM, smb);
        } else {
            float* yo = (step == N_STEPS - 1) ? out : g_y;
            do_tile(2, bm, bn, g_h, g_W2t, b2,
                    yo, nullptr, g_yr, ycur, g_k1,
                    D_DIM, H_DIM, smb);
        }

        // ---- publish completion ----
        __syncthreads();
        if (tid == 0) {
            __threadfence();
            atomicAdd(&g_cnt[phase * 64 + bmIdx], 1);
        }
    }
}

// ---------------- prep kernels ------------------------------------------------
__global__ void transpose_half(const float* __restrict__ in, __half* __restrict__ out,
                               int R, int C)
{
    __shared__ float t[32][33];
    const int bx = blockIdx.x * 32, by = blockIdx.y * 32;
    #pragma unroll
    for (int j = 0; j < 32; j += 8)
        t[threadIdx.y + j][threadIdx.x] = in[(size_t)(by + threadIdx.y + j) * C + bx + threadIdx.x];
    __syncthreads();
    #pragma unroll
    for (int j = 0; j < 32; j += 8)
        out[(size_t)(bx + threadIdx.y + j) * R + by + threadIdx.x] =
            __float2half_rn(t[threadIdx.x][threadIdx.y + j]);
}

// fp32->fp16 state copy, fused with counter reset
__global__ void prep_state(const float* __restrict__ in, __half* __restrict__ out, int n4)
{
    const int i = blockIdx.x * blockDim.x + threadIdx.x;
    if (i < 40 * 64) g_cnt[i] = 0;
    if (i < n4) {
        const float4 v = reinterpret_cast<const float4*>(in)[i];
        reinterpret_cast<__half2*>(out)[i * 2 + 0] = __floats2half2_rn(v.x, v.y);
        reinterpret_cast<__half2*>(out)[i * 2 + 1] = __floats2half2_rn(v.z, v.w);
    }
}

// ---------------- launch --------------------------------------------------------
extern "C" void kernel_launch(void* const* d_in, const int* in_sizes, int n_in,
                              void* d_out, int out_size)
{
    const float* y0 = (const float*)d_in[0];
    const float* W1 = (const float*)d_in[1];
    const float* b1 = (const float*)d_in[2];
    const float* W2 = (const float*)d_in[3];
    const float* b2 = (const float*)d_in[4];
    float* out = (float*)d_out;

    __half *pyr, *pW1t, *pW2t;
    cudaGetSymbolAddress((void**)&pyr,  g_yr);
    cudaGetSymbolAddress((void**)&pW1t, g_W1t);
    cudaGetSymbolAddress((void**)&pW2t, g_W2t);

    cudaFuncSetAttribute(heun_persistent,
                         cudaFuncAttributeMaxDynamicSharedMemorySize, SMEM_TOTAL);

    // grid: all CTAs must be co-resident (spin-wait safety)
    int dev = 0, sms = 0, occ = 0;
    cudaGetDevice(&dev);
    cudaDeviceGetAttribute(&sms, cudaDevAttrMultiProcessorCount, dev);
    cudaOccupancyMaxActiveBlocksPerMultiprocessor(&occ, heun_persistent, 128, SMEM_TOTAL);
    if (occ < 1) occ = 1;
    if (occ > 2) occ = 2;
    const int nCTA = sms * occ;

    // prep: weights -> K-major fp16; y0 -> fp16 copy + counter reset
    transpose_half<<<dim3(H_DIM / 32, D_DIM / 32), dim3(32, 8)>>>(W1, pW1t, D_DIM, H_DIM);
    transpose_half<<<dim3(D_DIM / 32, H_DIM / 32), dim3(32, 8)>>>(W2, pW2t, H_DIM, D_DIM);
    {
        const int n4 = M_BATCH * D_DIM / 4;
        prep_state<<<(n4 + 255) / 256, 256>>>(y0, pyr, n4);
    }

    heun_persistent<<<nCTA, 128, SMEM_TOTAL>>>(y0, b1, b2, out, nCTA);
}

// round 17
// speedup vs baseline: 1.0264x; 1.0020x over previous
#include <cuda_runtime.h>
#include <cuda_fp16.h>
#include <cstdint>
#include <cstddef>

#define M_BATCH 8192
#define D_DIM   512
#define H_DIM   2048
#define N_STEPS 10

// ---------------- scratch (device globals; no allocation allowed) ----------
__device__ float  g_y [M_BATCH * D_DIM];            // fp32 state
__device__ float  g_k1[M_BATCH * D_DIM];            // fp32 k1
__device__ __half g_yr[M_BATCH * D_DIM];            // fp16 copy of state (G1 A)
__device__ __half g_yt[M_BATCH * D_DIM];            // fp16 y + dt*k1   (G1 A)
__device__ __half g_h [M_BATCH * H_DIM];            // fp16 tanh hidden (G2 A)
__device__ __half g_W1t[(size_t)H_DIM * D_DIM];     // W1^T fp16, [N=H, K=D]
__device__ __half g_W2t[(size_t)D_DIM * H_DIM];     // W2^T fp16, [N=D, K=H]
__device__ int    g_cnt[40 * 64];                   // per-(phase, bm-row) counters

// ---------------- work-list constants ----------------------------------------
constexpr int TILES_G1   = 1024;   // 64 x 16 tiles of 128x128 (out 8192x2048)
constexpr int TILES_G2   = 256;    // 64 x  4 tiles of 128x128 (out 8192x512)
constexpr int TILES_STEP = 2 * TILES_G1 + 2 * TILES_G2;   // 2560
constexpr int TILES_TOT  = N_STEPS * TILES_STEP;          // 25600

// ---------------- helpers ----------------------------------------------------
__device__ __forceinline__ uint32_t smem_u32(const void* p) {
    uint32_t a;
    asm("{ .reg .u64 t; cvta.to.shared.u64 t, %1; cvt.u32.u64 %0, t; }" : "=r"(a) : "l"(p));
    return a;
}
// two tanh in one MUFU op (sm_75+ baseline feature)
__device__ __forceinline__ uint32_t tanh2_fast(float v0, float v1) {
    const __half2 hv = __floats2half2_rn(v0, v1);
    uint32_t u = *reinterpret_cast<const uint32_t*>(&hv);
    asm("tanh.approx.f16x2 %0, %0;" : "+r"(u));
    return u;
}
__device__ __forceinline__ void mma_f16(float c[4], const uint32_t a[4], const uint32_t b[2]) {
    asm volatile(
        "mma.sync.aligned.m16n8k16.row.col.f32.f16.f16.f32 "
        "{%0,%1,%2,%3}, {%4,%5,%6,%7}, {%8,%9}, {%0,%1,%2,%3};"
        : "+f"(c[0]), "+f"(c[1]), "+f"(c[2]), "+f"(c[3])
        : "r"(a[0]), "r"(a[1]), "r"(a[2]), "r"(a[3]), "r"(b[0]), "r"(b[1]));
}
__device__ __forceinline__ void ldsm_x4(uint32_t r[4], uint32_t addr) {
    asm volatile("ldmatrix.sync.aligned.m8n8.x4.shared.b16 {%0,%1,%2,%3}, [%4];"
        : "=r"(r[0]), "=r"(r[1]), "=r"(r[2]), "=r"(r[3]) : "r"(addr));
}
__device__ __forceinline__ int ld_acquire(const int* p) {
    int v;
    asm volatile("ld.acquire.gpu.global.b32 %0, [%1];" : "=r"(v) : "l"(p) : "memory");
    return v;
}
#define CP_ASYNC16(dst, src) \
    asm volatile("cp.async.cg.shared.global [%0], [%1], 16;" :: "r"(dst), "l"(src))
#define CP_COMMIT() asm volatile("cp.async.commit_group;" ::: "memory")
#define CP_WAIT(n)  asm volatile("cp.async.wait_group %0;" :: "n"(n) : "memory")

// ---------------- GEMM config ------------------------------------------------
// CTA tile 128x128, BK=64 (fp16), 3 smem stages, 128 threads (4 warps 2m x 2n,
// warp tile 64x64). Rows 128B with XOR-16B-chunk swizzle: chunk' = chunk^(row&7).
constexpr int ROWB  = 128;
constexpr int ASZ   = 128 * ROWB;          // 16384 B per operand stage
constexpr int STGB  = 2 * ASZ;             // 32768 B per stage (A + B)
constexpr int NSTG  = 3;
constexpr int SMEM_TOTAL = NSTG * STGB;    // 98304 B -> 2 CTAs/SM

// One 128x128 output tile of C = A @ Bw^T (+ fused epilogue by mode).
// mode 0: Ch = tanh_f16x2(acc + bias)
// mode 1: Cf = acc + bias (k1, fp32);  C2h = fp16(yin + 0.1*k1)   (yt)
// mode 2: yn = yin + 0.05*(k1in + (acc+bias)); Cf = yn; C2h = fp16(yn)
__device__ __forceinline__ void do_tile(
    int mode, int bm, int bn,
    const __half* __restrict__ A, const __half* __restrict__ Bw,
    const float* __restrict__ bias,
    float* __restrict__ Cf, __half* __restrict__ Ch, __half* __restrict__ C2h,
    const float* __restrict__ yin, const float* __restrict__ k1in,
    int N, int K, uint32_t smb)
{
    const int tid  = threadIdx.x;
    const int lane = tid & 31;
    const int wid  = tid >> 5;
    const int wm   = (wid & 1) * 64;
    const int wn   = (wid >> 1) * 64;
    const int g    = lane >> 2;
    const int tig  = lane & 3;
    const int ktiles = K / 64;

    const int e = lane & 7;
    const int m = lane >> 3;
    const uint32_t rowA = (uint32_t)(wm + (m & 1) * 8 + e) * ROWB;
    const int      ca   = m >> 1;
    const uint32_t rowB = (uint32_t)(wn + (m >> 1) * 8 + e) * ROWB;
    const int      cb   = m & 1;

    float acc[4][8][4];
    #pragma unroll
    for (int i = 0; i < 4; i++)
        #pragma unroll
        for (int j = 0; j < 8; j++)
            #pragma unroll
            for (int el = 0; el < 4; el++)
                acc[i][j][el] = 0.0f;

    auto load_tile = [&](int kt) {
        const int s = kt % NSTG;
        const uint32_t sa = smb + s * STGB;
        const uint32_t sb = sa + ASZ;
        #pragma unroll
        for (int i = 0; i < 8; i++) {
            const int t   = tid + i * 128;
            const int row = t >> 3;
            const int ch  = t & 7;
            const uint32_t off = (uint32_t)(row * ROWB + ((ch ^ (row & 7)) << 4));
            CP_ASYNC16(sa + off, A  + (size_t)(bm + row) * K + kt * 64 + ch * 8);
            CP_ASYNC16(sb + off, Bw + (size_t)(bn + row) * K + kt * 64 + ch * 8);
        }
    };

    #pragma unroll
    for (int kt = 0; kt < NSTG - 1; kt++) {
        if (kt < ktiles) load_tile(kt);
        CP_COMMIT();
    }

    for (int kt = 0; kt < ktiles; kt++) {
        if (kt + 1 < ktiles) { CP_WAIT(1); }
        else                 { CP_WAIT(0); }
        __syncthreads();

        if (kt + NSTG - 1 < ktiles) {
            load_tile(kt + NSTG - 1);
            CP_COMMIT();
        }

        const int s = kt % NSTG;
        const uint32_t sa = smb + s * STGB;
        const uint32_t sb = sa + ASZ;

        #pragma unroll
        for (int kq = 0; kq < 4; kq++) {
            uint32_t af[4][4], bf[8][2];
            #pragma unroll
            for (int mt = 0; mt < 4; mt++) {
                const uint32_t addr = sa + rowA + (uint32_t)(mt * 16) * ROWB
                                    + (uint32_t)(((2 * kq + ca) ^ e) << 4);
                ldsm_x4(af[mt], addr);
            }
            #pragma unroll
            for (int ntp = 0; ntp < 4; ntp++) {
                uint32_t r[4];
                const uint32_t addr = sb + rowB + (uint32_t)(ntp * 16) * ROWB
                                    + (uint32_t)(((2 * kq + cb) ^ e) << 4);
                ldsm_x4(r, addr);
                bf[2 * ntp + 0][0] = r[0];
                bf[2 * ntp + 0][1] = r[1];
                bf[2 * ntp + 1][0] = r[2];
                bf[2 * ntp + 1][1] = r[3];
            }
            #pragma unroll
            for (int mt = 0; mt < 4; mt++)
                #pragma unroll
                for (int nt = 0; nt < 8; nt++)
                    mma_f16(acc[mt][nt], af[mt], bf[nt]);
        }
    }

    // fused epilogue
    #pragma unroll
    for (int mt = 0; mt < 4; mt++) {
        #pragma unroll
        for (int nt = 0; nt < 8; nt++) {
            const int col = bn + wn + nt * 8 + tig * 2;
            const float bv0 = __ldg(&bias[col]);
            const float bv1 = __ldg(&bias[col + 1]);
            #pragma unroll
            for (int half = 0; half < 2; half++) {
                const int row = bm + wm + mt * 16 + g + half * 8;
                const size_t idx = (size_t)row * N + col;
                const float v0 = acc[mt][nt][half * 2 + 0] + bv0;
                const float v1 = acc[mt][nt][half * 2 + 1] + bv1;
                if (mode == 0) {
                    *reinterpret_cast<uint32_t*>(Ch + idx) = tanh2_fast(v0, v1);
                } else if (mode == 1) {
                    const float2 yv = *reinterpret_cast<const float2*>(yin + idx);
                    float2 o;  o.x = v0;  o.y = v1;
                    *reinterpret_cast<float2*>(Cf + idx) = o;
                    *reinterpret_cast<__half2*>(C2h + idx) =
                        __floats2half2_rn(yv.x + 0.1f * v0, yv.y + 0.1f * v1);
                } else {
                    const float2 yv = *reinterpret_cast<const float2*>(yin + idx);
                    const float2 kv = *reinterpret_cast<const float2*>(k1in + idx);
                    float2 o;
                    o.x = yv.x + 0.05f * (kv.x + v0);
                    o.y = yv.y + 0.05f * (kv.y + v1);
                    *reinterpret_cast<float2*>(Cf + idx) = o;
                    *reinterpret_cast<__half2*>(C2h + idx) = __floats2half2_rn(o.x, o.y);
                }
            }
        }
    }
}

// ---------------- persistent scheduler kernel ---------------------------------
__global__ void __launch_bounds__(128, 2)
heun_persistent(const float* __restrict__ y0, const float* __restrict__ b1,
                const float* __restrict__ b2, float* __restrict__ out, int nCTA)
{
    extern __shared__ char sm[];
    const uint32_t smb = smem_u32(sm);
    const int tid = threadIdx.x;

    for (int item = blockIdx.x; item < TILES_TOT; item += nCTA) {
        // ---- decode work item -> (step, q, tile) ----
        const int step = item / TILES_STEP;
        const int r    = item - step * TILES_STEP;
        int q, t;
        if      (r < TILES_G1)                 { q = 0; t = r; }
        else if (r < TILES_G1 + TILES_G2)      { q = 1; t = r - TILES_G1; }
        else if (r < 2 * TILES_G1 + TILES_G2)  { q = 2; t = r - TILES_G1 - TILES_G2; }
        else                                   { q = 3; t = r - 2 * TILES_G1 - TILES_G2; }
        const int phase = step * 4 + q;
        const bool isG1 = (q & 1) == 0;
        const int bmIdx = isG1 ? (t >> 4) : (t >> 2);
        const int bn    = (isG1 ? (t & 15) : (t & 3)) * 128;
        const int bm    = bmIdx * 128;

        // ---- wait for producer phase (per bm row) ----
        if (phase > 0) {
            const int target = isG1 ? 4 : 16;     // prev phase tiles per bm row
            const int* cp = &g_cnt[(phase - 1) * 64 + bmIdx];
            if (tid == 0) {
                while (ld_acquire(cp) < target) __nanosleep(64);
            }
            __syncthreads();
        }

        // ---- dispatch ----
        const float* ycur = (step == 0) ? y0 : g_y;
        if (isG1) {
            const __half* A = (q == 0) ? g_yr : g_yt;
            do_tile(0, bm, bn, A, g_W1t, b1,
                    nullptr, g_h, nullptr, nullptr, nullptr,
                    H_DIM, D_DIM, smb);
        } else if (q == 1) {
            do_tile(1, bm, bn, g_h, g_W2t, b2,
                    g_k1, nullptr, g_yt, ycur, nullptr,
                    D_DIM, H_DIM, smb);
        } else {
            float* yo = (step == N_STEPS - 1) ? out : g_y;
            do_tile(2, bm, bn, g_h, g_W2t, b2,
                    yo, nullptr, g_yr, ycur, g_k1,
                    D_DIM, H_DIM, smb);
        }

        // ---- publish completion ----
        __syncthreads();
        if (tid == 0) {
            __threadfence();
            atomicAdd(&g_cnt[phase * 64 + bmIdx], 1);
        }
    }
}

// ---------------- prep kernels ------------------------------------------------
__global__ void transpose_half(const float* __restrict__ in, __half* __restrict__ out,
                               int R, int C)
{
    __shared__ float t[32][33];
    const int bx = blockIdx.x * 32, by = blockIdx.y * 32;
    #pragma unroll
    for (int j = 0; j < 32; j += 8)
        t[threadIdx.y + j][threadIdx.x] = in[(size_t)(by + threadIdx.y + j) * C + bx + threadIdx.x];
    __syncthreads();
    #pragma unroll
    for (int j = 0; j < 32; j += 8)
        out[(size_t)(bx + threadIdx.y + j) * R + by + threadIdx.x] =
            __float2half_rn(t[threadIdx.x][threadIdx.y + j]);
}

// fp32->fp16 state copy, fused with counter reset
__global__ void prep_state(const float* __restrict__ in, __half* __restrict__ out, int n4)
{
    const int i = blockIdx.x * blockDim.x + threadIdx.x;
    if (i < 40 * 64) g_cnt[i] = 0;
    if (i < n4) {
        const float4 v = reinterpret_cast<const float4*>(in)[i];
        reinterpret_cast<__half2*>(out)[i * 2 + 0] = __floats2half2_rn(v.x, v.y);
        reinterpret_cast<__half2*>(out)[i * 2 + 1] = __floats2half2_rn(v.z, v.w);
    }
}

// ---------------- launch --------------------------------------------------------
extern "C" void kernel_launch(void* const* d_in, const int* in_sizes, int n_in,
                              void* d_out, int out_size)
{
    const float* y0 = (const float*)d_in[0];
    const float* W1 = (const float*)d_in[1];
    const float* b1 = (const float*)d_in[2];
    const float* W2 = (const float*)d_in[3];
    const float* b2 = (const float*)d_in[4];
    float* out = (float*)d_out;

    __half *pyr, *pW1t, *pW2t;
    cudaGetSymbolAddress((void**)&pyr,  g_yr);
    cudaGetSymbolAddress((void**)&pW1t, g_W1t);
    cudaGetSymbolAddress((void**)&pW2t, g_W2t);

    cudaFuncSetAttribute(heun_persistent,
                         cudaFuncAttributeMaxDynamicSharedMemorySize, SMEM_TOTAL);

    // grid: all CTAs must be co-resident (spin-wait safety)
    int dev = 0, sms = 0, occ = 0;
    cudaGetDevice(&dev);
    cudaDeviceGetAttribute(&sms, cudaDevAttrMultiProcessorCount, dev);
    cudaOccupancyMaxActiveBlocksPerMultiprocessor(&occ, heun_persistent, 128, SMEM_TOTAL);
    if (occ < 1) occ = 1;
    if (occ > 2) occ = 2;
    const int nCTA = sms * occ;

    // prep: weights -> K-major fp16; y0 -> fp16 copy + counter reset
    transpose_half<<<dim3(H_DIM / 32, D_DIM / 32), dim3(32, 8)>>>(W1, pW1t, D_DIM, H_DIM);
    transpose_half<<<dim3(D_DIM / 32, H_DIM / 32), dim3(32, 8)>>>(W2, pW2t, H_DIM, D_DIM);
    {
        const int n4 = M_BATCH * D_DIM / 4;
        prep_state<<<(n4 + 255) / 256, 256>>>(y0, pyr, n4);
    }

    heun_persistent<<<nCTA, 128, SMEM_TOTAL>>>(y0, b1, b2, out, nCTA);
}